// round 2
// baseline (speedup 1.0000x reference)
#include <cuda_runtime.h>
#include <cuda_bf16.h>
#include <cstdint>

// ---------------------------------------------------------------------------
// coordx_net: fx = premerge(x*bw0+bb0) [1024,256], fy likewise,
// h[i,j,n] = sin( sum_k fx[i,k]*fy[j,k]*qw1[n,k] + qb1[n] )
// out[c,j,i] = sigmoid( sum_n h[i,j,n]*qw2[c,n] + qb2[c] )
// Restructure: for fixed j it is a GEMM with A = fx (x) fy_j.
// ---------------------------------------------------------------------------

#define H 1024
#define W 1024
#define HID 256
#define C 3

// scratch for branch features
__device__ __align__(16) float g_fx[H * HID];
__device__ __align__(16) float g_fy[W * HID];

// ---------------- fast sine: pi range reduction + deg-9 Taylor -------------
__device__ __forceinline__ float fast_sin(float x) {
    const float INV_PI = 0.318309886183790671f;
    float k = rintf(x * INV_PI);
    float r = fmaf(-k, 3.14159274101257324f, x);   // x - k*pi_hi
    r = fmaf(k, 8.74227765734758577e-8f, r);       // - k*pi_lo
    float s = r * r;
    float p = fmaf(s, 2.75573192e-6f, -1.98412698e-4f);
    p = fmaf(s, p, 8.33333333e-3f);
    p = fmaf(s, p, -1.66666667e-1f);
    float res = fmaf(s * r, p, r);                 // r + r^3 * P(r^2)
    int ki = (int)k;
    return (ki & 1) ? -res : res;
}

// ---------------- kernel 1: branch + premerge for both axes ----------------
// grid: (64, 2), 256 threads. Each CTA: 16 rows of one axis.
__device__ __forceinline__ void dense_layer(
    const float (*hin)[HID], float (*hout)[HID],
    const float* __restrict__ pw, const float* __restrict__ pb, int t)
{
    float acc[16];
    float bias = pb[t];
#pragma unroll
    for (int r = 0; r < 16; r++) acc[r] = bias;
    const float4* pw4 = (const float4*)pw;
#pragma unroll 4
    for (int k4 = 0; k4 < HID / 4; k4++) {
        float4 w4 = pw4[t * (HID / 4) + k4];
#pragma unroll
        for (int r = 0; r < 16; r++) {
            float4 hv = *(const float4*)&hin[r][k4 * 4];
            acc[r] = fmaf(hv.x, w4.x, acc[r]);
            acc[r] = fmaf(hv.y, w4.y, acc[r]);
            acc[r] = fmaf(hv.z, w4.z, acc[r]);
            acc[r] = fmaf(hv.w, w4.w, acc[r]);
        }
    }
#pragma unroll
    for (int r = 0; r < 16; r++) hout[r][t] = fast_sin(acc[r]);
}

__global__ void branch_kernel(
    const float* __restrict__ x, const float* __restrict__ y,
    const float* __restrict__ bw0, const float* __restrict__ bb0,
    const float* __restrict__ bw1, const float* __restrict__ bb1,
    const float* __restrict__ pw1, const float* __restrict__ pb1,
    const float* __restrict__ pw2, const float* __restrict__ pb2)
{
    int axis = blockIdx.y;
    const float* coord = axis ? y : x;
    const float* bw = axis ? bw1 : bw0;
    const float* bb = axis ? bb1 : bb0;
    float* outf = axis ? g_fy : g_fx;
    int r0 = blockIdx.x * 16;
    int t = threadIdx.x;

    __shared__ __align__(16) float hA[16][HID];
    __shared__ __align__(16) float hB[16][HID];

    float w = bw[t], b = bb[t];
#pragma unroll
    for (int r = 0; r < 16; r++)
        hA[r][t] = fast_sin(fmaf(coord[r0 + r], w, b));
    __syncthreads();
    dense_layer(hA, hB, pw1, pb1, t);
    __syncthreads();
    dense_layer(hB, hA, pw2, pb2, t);
    __syncthreads();
#pragma unroll
    for (int r = 0; r < 16; r++)
        outf[(r0 + r) * HID + t] = hA[r][t];
}

// ---------------- kernel 2: fused per-j GEMM + sin + GEMV + sigmoid --------
// grid: (H/64, W). CTA: 64 i x 256 n, fixed j. 256 threads, 8x8 acc each.
#define TM 64
#define KC 32
#define AP 64      // As row stride (floats)
#define BP 260     // Bs row stride (floats), 16B-aligned
#define SMEM_FLOATS (HID * AP + KC * BP)

__global__ __launch_bounds__(256, 2)
void fused_kernel(
    const float* __restrict__ qw1, const float* __restrict__ qb1,
    const float* __restrict__ qw2, const float* __restrict__ qb2,
    float* __restrict__ out)
{
    extern __shared__ float smem[];
    float* As = smem;                 // [HID][AP]  : A[k][i] = fx[i0+i][k]*fy[j][k]
    float* Bs = smem + HID * AP;      // [KC][BP]   : B[kk][n] = qw1[n][k0+kk]

    int tid = threadIdx.x;
    int j = blockIdx.y;
    int i0 = blockIdx.x * TM;

    const float4* fx4 = (const float4*)g_fx;
    const float4* fy4 = (const float4*)g_fy;
    const float4* qw1_4 = (const float4*)qw1;

    // Build As (one-shot, stays resident for all K chunks)
    for (int e = tid; e < TM * (HID / 4); e += 256) {
        int i = e & (TM - 1);
        int k4 = e >> 6;              // TM=64 -> e/64
        float4 fv = fx4[(i0 + i) * (HID / 4) + k4];
        float4 gv = fy4[j * (HID / 4) + k4];
        int k = k4 * 4;
        As[(k + 0) * AP + i] = fv.x * gv.x;
        As[(k + 1) * AP + i] = fv.y * gv.y;
        As[(k + 2) * AP + i] = fv.z * gv.z;
        As[(k + 3) * AP + i] = fv.w * gv.w;
    }

    float acc[8][8];
#pragma unroll
    for (int p = 0; p < 8; p++)
#pragma unroll
        for (int q = 0; q < 8; q++) acc[p][q] = 0.f;

    int ti = (tid & 7) * 8;           // i sub-tile base
    int tn = (tid >> 3) * 8;          // n sub-tile base

    for (int k0 = 0; k0 < HID; k0 += KC) {
        __syncthreads();              // prior readers of Bs done (and As built)
        // load B chunk: Bs[kk][n] = qw1[n][k0+kk]   (coalesced 128B rows)
        for (int e = tid; e < HID * (KC / 4); e += 256) {
            int n = e >> 3;
            int k4 = e & 7;
            float4 w4 = qw1_4[n * (HID / 4) + (k0 >> 2) + k4];
            int kk = k4 * 4;
            Bs[(kk + 0) * BP + n] = w4.x;
            Bs[(kk + 1) * BP + n] = w4.y;
            Bs[(kk + 2) * BP + n] = w4.z;
            Bs[(kk + 3) * BP + n] = w4.w;
        }
        __syncthreads();

#pragma unroll 8
        for (int kk = 0; kk < KC; kk++) {
            const float* ap = &As[(k0 + kk) * AP + ti];
            const float* bp = &Bs[kk * BP + tn];
            float4 a0 = *(const float4*)(ap);
            float4 a1 = *(const float4*)(ap + 4);
            float4 b0 = *(const float4*)(bp);
            float4 b1 = *(const float4*)(bp + 4);
            float av[8] = {a0.x, a0.y, a0.z, a0.w, a1.x, a1.y, a1.z, a1.w};
            float bv[8] = {b0.x, b0.y, b0.z, b0.w, b1.x, b1.y, b1.z, b1.w};
#pragma unroll
            for (int p = 0; p < 8; p++)
#pragma unroll
                for (int q = 0; q < 8; q++)
                    acc[p][q] = fmaf(av[p], bv[q], acc[p][q]);
        }
    }

    // Epilogue: h = sin(acc + qb1[n]) -> reuse As as Hs[n][i]
    __syncthreads();
    float* Hs = As;
#pragma unroll
    for (int q = 0; q < 8; q++) {
        float bq = __ldg(&qb1[tn + q]);
#pragma unroll
        for (int p = 0; p < 8; p++)
            Hs[(tn + q) * AP + ti + p] = fast_sin(acc[p][q] + bq);
    }
    __syncthreads();

    // 256 -> 3 GEMV + sigmoid, deterministic (one thread per (i,c))
    if (tid < TM * C) {
        int i = tid & (TM - 1);
        int c = tid >> 6;
        float s = __ldg(&qb2[c]);
        const float* wr = qw2 + c * HID;
#pragma unroll 8
        for (int n = 0; n < HID; n++)
            s = fmaf(Hs[n * AP + i], __ldg(&wr[n]), s);
        // out[c, j, i]
        out[((unsigned)c * W + j) * H + i0 + i] = 1.f / (1.f + __expf(-s));
    }
}

// ---------------------------------------------------------------------------
extern "C" void kernel_launch(void* const* d_in, const int* in_sizes, int n_in,
                              void* d_out, int out_size)
{
    const float* x   = (const float*)d_in[0];
    const float* y   = (const float*)d_in[1];
    const float* bw0 = (const float*)d_in[2];
    const float* bb0 = (const float*)d_in[3];
    const float* bw1 = (const float*)d_in[4];
    const float* bb1 = (const float*)d_in[5];
    const float* pw1 = (const float*)d_in[6];
    const float* pb1 = (const float*)d_in[7];
    const float* pw2 = (const float*)d_in[8];
    const float* pb2 = (const float*)d_in[9];
    const float* qw1 = (const float*)d_in[10];
    const float* qb1 = (const float*)d_in[11];
    const float* qw2 = (const float*)d_in[12];
    const float* qb2 = (const float*)d_in[13];
    float* out = (float*)d_out;

    const int smem_bytes = SMEM_FLOATS * (int)sizeof(float); // 98816 B
    cudaFuncSetAttribute(fused_kernel,
                         cudaFuncAttributeMaxDynamicSharedMemorySize, smem_bytes);

    branch_kernel<<<dim3(H / 16, 2), 256>>>(x, y, bw0, bb0, bw1, bb1,
                                            pw1, pb1, pw2, pb2);
    fused_kernel<<<dim3(H / TM, W), 256, smem_bytes>>>(qw1, qb1, qw2, qb2, out);
}

// round 5
// speedup vs baseline: 2.7537x; 2.7537x over previous
#include <cuda_runtime.h>
#include <cuda_bf16.h>
#include <cstdint>

#define H 1024
#define W 1024
#define HID 256
#define C 3

// ---------------------------------------------------------------------------
// global scratch
// ---------------------------------------------------------------------------
__device__ __align__(16) float g_fx[H * HID];
__device__ __align__(16) float g_fy[W * HID];
// qw1 split into bf16 hi/lo, SW128-swizzled K-major tiles.
// chunk c (k0=64c), half h (0=hi,1=lo): 32KB tile at (c*2+h)*32768
__device__ __align__(16) unsigned char g_qsplit[4 * 2 * 32768];

// ---------------- fast sine: pi range reduction + deg-9 Taylor -------------
__device__ __forceinline__ float fast_sin(float x) {
    const float INV_PI = 0.318309886183790671f;
    float k = rintf(x * INV_PI);
    float r = fmaf(-k, 3.14159274101257324f, x);
    r = fmaf(k, 8.74227765734758577e-8f, r);
    float s = r * r;
    float p = fmaf(s, 2.75573192e-6f, -1.98412698e-4f);
    p = fmaf(s, p, 8.33333333e-3f);
    p = fmaf(s, p, -1.66666667e-1f);
    float res = fmaf(s * r, p, r);
    int ki = (int)k;
    return (ki & 1) ? -res : res;
}

// ---------------- helpers --------------------------------------------------
__device__ __forceinline__ uint32_t smem_u32(const void* p) {
    uint32_t a;
    asm("{ .reg .u64 t; cvta.to.shared.u64 t, %1; cvt.u32.u64 %0, t; }"
        : "=r"(a) : "l"(p));
    return a;
}
__device__ __forceinline__ void ldsm_x4(uint32_t* r, uint32_t addr) {
    asm volatile("ldmatrix.sync.aligned.m8n8.x4.shared.b16 {%0,%1,%2,%3}, [%4];"
                 : "=r"(r[0]), "=r"(r[1]), "=r"(r[2]), "=r"(r[3]) : "r"(addr));
}
__device__ __forceinline__ void mma_bf16(float* c, const uint32_t* a,
                                         const uint32_t* b) {
    asm volatile(
        "mma.sync.aligned.m16n8k16.row.col.f32.bf16.bf16.f32 "
        "{%0,%1,%2,%3}, {%4,%5,%6,%7}, {%8,%9}, {%0,%1,%2,%3};"
        : "+f"(c[0]), "+f"(c[1]), "+f"(c[2]), "+f"(c[3])
        : "r"(a[0]), "r"(a[1]), "r"(a[2]), "r"(a[3]), "r"(b[0]), "r"(b[1]));
}
#define CP_ASYNC16(dst, src) \
    asm volatile("cp.async.cg.shared.global [%0], [%1], 16;" \
                 :: "r"(dst), "l"(src))
#define CP_COMMIT() asm volatile("cp.async.commit_group;")
#define CP_WAIT0()  asm volatile("cp.async.wait_group 0;" ::: "memory")

__device__ __forceinline__ uint32_t packbf2(float hi, float lo) {
    uint32_t r;
    asm("cvt.rn.bf16x2.f32 %0, %1, %2;" : "=r"(r) : "f"(hi), "f"(lo));
    return r;
}
__device__ __forceinline__ float bf_lo(uint32_t w) { return __int_as_float(w << 16); }
__device__ __forceinline__ float bf_hi(uint32_t w) { return __int_as_float(w & 0xffff0000u); }

// ---------------- kernel 0: split+swizzle qw1 ------------------------------
__global__ void split_qw1_kernel(const float* __restrict__ qw1) {
    int idx = blockIdx.x * 256 + threadIdx.x;   // 0..32767 bf16x2 words
    int n = idx >> 7;                           // row 0..255
    int kw = idx & 127;                         // k-pair
    int k = kw * 2;
    int cch = k >> 6;                           // chunk
    int kk = k & 63;
    float w0 = qw1[n * HID + k];
    float w1 = qw1[n * HID + k + 1];
    uint32_t hi = packbf2(w1, w0);
    float r0 = w0 - bf_lo(hi);
    float r1 = w1 - bf_hi(hi);
    uint32_t lo = packbf2(r1, r0);
    uint32_t off = ((n >> 3) << 10) + ((n & 7) << 7) + kk * 2;
    uint32_t sw = off ^ ((off >> 3) & 0x70);
    *(uint32_t*)(g_qsplit + (cch * 2 + 0) * 32768 + sw) = hi;
    *(uint32_t*)(g_qsplit + (cch * 2 + 1) * 32768 + sw) = lo;
}

// ---------------- kernel 1: branch + premerge ------------------------------
__device__ __forceinline__ void dense_layer(
    const float (*hin)[HID], float (*hout)[HID],
    const float* __restrict__ pw, const float* __restrict__ pb, int t)
{
    float acc[16];
    float bias = pb[t];
#pragma unroll
    for (int r = 0; r < 16; r++) acc[r] = bias;
    const float4* pw4 = (const float4*)pw;
#pragma unroll 4
    for (int k4 = 0; k4 < HID / 4; k4++) {
        float4 w4 = pw4[t * (HID / 4) + k4];
#pragma unroll
        for (int r = 0; r < 16; r++) {
            float4 hv = *(const float4*)&hin[r][k4 * 4];
            acc[r] = fmaf(hv.x, w4.x, acc[r]);
            acc[r] = fmaf(hv.y, w4.y, acc[r]);
            acc[r] = fmaf(hv.z, w4.z, acc[r]);
            acc[r] = fmaf(hv.w, w4.w, acc[r]);
        }
    }
#pragma unroll
    for (int r = 0; r < 16; r++) hout[r][t] = fast_sin(acc[r]);
}

__global__ void branch_kernel(
    const float* __restrict__ x, const float* __restrict__ y,
    const float* __restrict__ bw0, const float* __restrict__ bb0,
    const float* __restrict__ bw1, const float* __restrict__ bb1,
    const float* __restrict__ pw1, const float* __restrict__ pb1,
    const float* __restrict__ pw2, const float* __restrict__ pb2)
{
    int axis = blockIdx.y;
    const float* coord = axis ? y : x;
    const float* bw = axis ? bw1 : bw0;
    const float* bb = axis ? bb1 : bb0;
    float* outf = axis ? g_fy : g_fx;
    int r0 = blockIdx.x * 16;
    int t = threadIdx.x;

    __shared__ __align__(16) float hA[16][HID];
    __shared__ __align__(16) float hB[16][HID];

    float w = bw[t], b = bb[t];
#pragma unroll
    for (int r = 0; r < 16; r++)
        hA[r][t] = fast_sin(fmaf(coord[r0 + r], w, b));
    __syncthreads();
    dense_layer(hA, hB, pw1, pb1, t);
    __syncthreads();
    dense_layer(hB, hA, pw2, pb2, t);
    __syncthreads();
#pragma unroll
    for (int r = 0; r < 16; r++)
        outf[(r0 + r) * HID + t] = hA[r][t];
}

// ---------------- kernel 2: warp-MMA fused GEMM + epilogue -----------------
// grid (8, 1024): i0 = bx*128, j = by. 512 threads = 16 warps (4 M x 4 N).
// Warp tile 32(m) x 64(n). K = 4 chunks of 64, double-buffered.
// SMEM map:
//   0     fys (1KB) | 1024 qb1s (1KB) | 2048 qw2s (3KB) | 5120 qb2s
//   5632  part[128][4][3] f32 (6KB)
//   12288 stage0: Ah 16K | Al 16K | Bh 32K | Bl 32K   (96KB)
//   110592 stage1: same
#define SM_FY   0
#define SM_QB1  1024
#define SM_QW2  2048
#define SM_QB2  5120
#define SM_PART 5632
#define SM_STG  12288
#define STG_SZ  98304
#define A_HALF  16384
#define B_OFF   32768
#define SMEM_TOTAL (SM_STG + 2 * STG_SZ)   // 208896

__global__ __launch_bounds__(512, 1)
void fused_mma_kernel(
    const float* __restrict__ qb1, const float* __restrict__ qw2,
    const float* __restrict__ qb2, float* __restrict__ out)
{
    extern __shared__ __align__(1024) char smem[];
    const uint32_t sb = smem_u32(smem);
    const int tid = threadIdx.x;
    const int wid = tid >> 5;
    const int lane = tid & 31;
    const int wm = wid & 3;          // warp row (M)
    const int wn = wid >> 2;         // warp col (N)
    const int m0w = wm * 32;
    const int n0w = wn * 64;
    const int j = blockIdx.y;
    const int i0 = blockIdx.x * 128;

    float* fys  = (float*)(smem + SM_FY);
    float* qb1s = (float*)(smem + SM_QB1);
    float* qw2s = (float*)(smem + SM_QW2);
    float* qb2s = (float*)(smem + SM_QB2);
    float* part = (float*)(smem + SM_PART);

    // stage small arrays
    if (tid < 256) {
        fys[tid] = g_fy[j * HID + tid];
        qb1s[tid] = qb1[tid];
    }
    for (int e = tid; e < 3 * HID; e += 512) qw2s[e] = qw2[e];
    if (tid < 3) qb2s[tid] = qb2[tid];
    __syncthreads();

    // ---- A build: thread -> row r = tid/4, k-quarter kq = (tid%4)*16 ----
    const int rA = tid >> 2;
    const int kq = (tid & 3) << 4;
    const uint32_t rowoff = ((rA >> 3) << 10) + ((rA & 7) << 7);
    const uint32_t rxor = (rA & 7) << 4;

    auto build_A = [&](int c, uint32_t stg) {
        const float4* fxp = (const float4*)(g_fx + (i0 + rA) * HID + c * 64 + kq);
        const float4* fyp = (const float4*)(fys + c * 64 + kq);
        uint32_t hw[8], lw[8];
#pragma unroll
        for (int q = 0; q < 4; q++) {
            float4 f = fxp[q];
            float4 g = fyp[q];
            float p0 = f.x * g.x, p1 = f.y * g.y, p2 = f.z * g.z, p3 = f.w * g.w;
            uint32_t h01 = packbf2(p1, p0);
            uint32_t h23 = packbf2(p3, p2);
            hw[q * 2] = h01; hw[q * 2 + 1] = h23;
            lw[q * 2] = packbf2(p1 - bf_hi(h01), p0 - bf_lo(h01));
            lw[q * 2 + 1] = packbf2(p3 - bf_hi(h23), p2 - bf_lo(h23));
        }
        char* base = smem + stg;     // stage base (A_hi at 0, A_lo at +16384)
        uint32_t c0 = (uint32_t)(kq * 2);          // byte col 0,32,64,96
        uint32_t o0 = rowoff + (c0 ^ rxor);
        uint32_t o1 = rowoff + ((c0 + 16) ^ rxor);
        *(uint4*)(base + o0) = make_uint4(hw[0], hw[1], hw[2], hw[3]);
        *(uint4*)(base + o1) = make_uint4(hw[4], hw[5], hw[6], hw[7]);
        *(uint4*)(base + A_HALF + o0) = make_uint4(lw[0], lw[1], lw[2], lw[3]);
        *(uint4*)(base + A_HALF + o1) = make_uint4(lw[4], lw[5], lw[6], lw[7]);
    };
    auto copy_B = [&](int c, uint32_t stg_u32) {
        const char* src = (const char*)g_qsplit + c * 65536;
        uint32_t dst = stg_u32 + B_OFF;
#pragma unroll
        for (int e = 0; e < 8; e++) {
            uint32_t off = (uint32_t)(e * 512 + tid) * 16;
            CP_ASYNC16(dst + off, src + off);
        }
        CP_COMMIT();
    };

    // ---- LDSM per-thread row/col components (swizzle applied per k-step) --
    uint32_t rowA[2], xorA[2], colA;
    uint32_t rowB[4], xorB[4], colB;
    colA = (uint32_t)((lane >> 4) << 4);           // 0 or 16 bytes (k0/k8)
#pragma unroll
    for (int mb = 0; mb < 2; mb++) {
        int r = m0w + mb * 16 + (lane & 15);
        rowA[mb] = ((r >> 3) << 10) + ((r & 7) << 7);
        xorA[mb] = (uint32_t)((r & 7) << 4);
    }
    colB = (uint32_t)(((lane >> 3) & 1) << 4);     // 0 or 16 bytes (k0/k8)
#pragma unroll
    for (int nb = 0; nb < 4; nb++) {
        int r = n0w + nb * 16 + (lane & 7) + ((lane >> 4) << 3);
        rowB[nb] = ((r >> 3) << 10) + ((r & 7) << 7);
        xorB[nb] = (uint32_t)((r & 7) << 4);
    }

    float acc[2][8][4];
#pragma unroll
    for (int mb = 0; mb < 2; mb++)
#pragma unroll
        for (int nx = 0; nx < 8; nx++)
#pragma unroll
            for (int e = 0; e < 4; e++) acc[mb][nx][e] = 0.f;

    // ---- prologue: chunk 0 ----
    {
        uint32_t stg = sb + SM_STG;
        copy_B(0, stg);
        build_A(0, SM_STG);
        CP_WAIT0();
        __syncthreads();
    }

    // ---- main loop ----
    for (int c = 0; c < 4; c++) {
        const uint32_t stg = sb + SM_STG + (uint32_t)(c & 1) * STG_SZ;
        if (c < 3) {
            uint32_t nstg = sb + SM_STG + (uint32_t)((c + 1) & 1) * STG_SZ;
            copy_B(c + 1, nstg);
            build_A(c + 1, SM_STG + ((c + 1) & 1) * STG_SZ);
        }
#pragma unroll
        for (int s = 0; s < 4; s++) {
            const uint32_t ks = (uint32_t)(s * 32);
            uint32_t ah[2][4], al[2][4];
#pragma unroll
            for (int mb = 0; mb < 2; mb++) {
                uint32_t adr = stg + rowA[mb] + ((colA + ks) ^ xorA[mb]);
                ldsm_x4(ah[mb], adr);
                ldsm_x4(al[mb], adr + A_HALF);
            }
#pragma unroll
            for (int nb = 0; nb < 4; nb++) {
                uint32_t bh[4], bl[4];
                uint32_t adr = stg + B_OFF + rowB[nb] + ((colB + ks) ^ xorB[nb]);
                ldsm_x4(bh, adr);
                ldsm_x4(bl, adr + 32768);
#pragma unroll
                for (int mb = 0; mb < 2; mb++) {
#pragma unroll
                    for (int sub = 0; sub < 2; sub++) {
                        float* acp = acc[mb][nb * 2 + sub];
                        mma_bf16(acp, ah[mb], bh + sub * 2);
                        mma_bf16(acp, ah[mb], bl + sub * 2);
                        mma_bf16(acp, al[mb], bh + sub * 2);
                    }
                }
            }
        }
        if (c < 3) {
            CP_WAIT0();
            __syncthreads();
        }
    }

    // ---- epilogue: sin(acc+qb1) -> 3-ch partial GEMV -> reduce -> out ----
    float p[12];                      // [mb][rh][c]
#pragma unroll
    for (int e = 0; e < 12; e++) p[e] = 0.f;
#pragma unroll
    for (int mb = 0; mb < 2; mb++) {
#pragma unroll
        for (int nx = 0; nx < 8; nx++) {
            int nbase = n0w + nx * 8 + (lane & 3) * 2;
#pragma unroll
            for (int e = 0; e < 4; e++) {
                int n = nbase + (e & 1);
                int rh = e >> 1;
                float hv = fast_sin(acc[mb][nx][e] + qb1s[n]);
                p[(mb * 2 + rh) * 3 + 0] = fmaf(hv, qw2s[n], p[(mb * 2 + rh) * 3 + 0]);
                p[(mb * 2 + rh) * 3 + 1] = fmaf(hv, qw2s[256 + n], p[(mb * 2 + rh) * 3 + 1]);
                p[(mb * 2 + rh) * 3 + 2] = fmaf(hv, qw2s[512 + n], p[(mb * 2 + rh) * 3 + 2]);
            }
        }
    }
#pragma unroll
    for (int d = 1; d <= 2; d <<= 1)
#pragma unroll
        for (int e = 0; e < 12; e++)
            p[e] += __shfl_xor_sync(0xffffffffu, p[e], d);

    if ((lane & 3) == 0) {
#pragma unroll
        for (int mb = 0; mb < 2; mb++)
#pragma unroll
            for (int rh = 0; rh < 2; rh++) {
                int m = m0w + mb * 16 + (lane >> 2) + rh * 8;
#pragma unroll
                for (int cc = 0; cc < 3; cc++)
                    part[(m * 4 + wn) * 3 + cc] = p[(mb * 2 + rh) * 3 + cc];
            }
    }
    __syncthreads();

    if (tid < 384) {
        int m = tid & 127;
        int cc = tid >> 7;
        float s = qb2s[cc];
#pragma unroll
        for (int v = 0; v < 4; v++) s += part[(m * 4 + v) * 3 + cc];
        out[((unsigned)cc * W + j) * H + i0 + m] = 1.f / (1.f + __expf(-s));
    }
}

// ---------------------------------------------------------------------------
extern "C" void kernel_launch(void* const* d_in, const int* in_sizes, int n_in,
                              void* d_out, int out_size)
{
    const float* x   = (const float*)d_in[0];
    const float* y   = (const float*)d_in[1];
    const float* bw0 = (const float*)d_in[2];
    const float* bb0 = (const float*)d_in[3];
    const float* bw1 = (const float*)d_in[4];
    const float* bb1 = (const float*)d_in[5];
    const float* pw1 = (const float*)d_in[6];
    const float* pb1 = (const float*)d_in[7];
    const float* pw2 = (const float*)d_in[8];
    const float* pb2 = (const float*)d_in[9];
    const float* qw1 = (const float*)d_in[10];
    const float* qb1 = (const float*)d_in[11];
    const float* qw2 = (const float*)d_in[12];
    const float* qb2 = (const float*)d_in[13];
    float* out = (float*)d_out;

    cudaFuncSetAttribute(fused_mma_kernel,
                         cudaFuncAttributeMaxDynamicSharedMemorySize, SMEM_TOTAL);

    split_qw1_kernel<<<128, 256>>>(qw1);
    branch_kernel<<<dim3(H / 16, 2), 256>>>(x, y, bw0, bb0, bw1, bb1,
                                            pw1, pb1, pw2, pb2);
    fused_mma_kernel<<<dim3(8, 1024), 512, SMEM_TOTAL>>>(qb1, qw2, qb2, out);
}

// round 6
// speedup vs baseline: 4.6763x; 1.6982x over previous
#include <cuda_runtime.h>
#include <cuda_bf16.h>
#include <cuda_fp16.h>
#include <cstdint>

#define H 1024
#define W 1024
#define HID 256
#define C 3

// ---------------------------------------------------------------------------
// global scratch
// ---------------------------------------------------------------------------
__device__ __align__(16) float g_fx[H * HID];
__device__ __align__(16) float g_fy[W * HID];
// qw1 as fp16, SW128-swizzled K-major tiles. chunk c (k0=64c): 32KB at c*32768
__device__ __align__(16) unsigned char g_qpack[4 * 32768];

// ---------------- fast sine: pi range reduction + deg-9 Taylor -------------
__device__ __forceinline__ float fast_sin(float x) {
    const float INV_PI = 0.318309886183790671f;
    float k = rintf(x * INV_PI);
    float r = fmaf(-k, 3.14159274101257324f, x);
    r = fmaf(k, 8.74227765734758577e-8f, r);
    float s = r * r;
    float p = fmaf(s, 2.75573192e-6f, -1.98412698e-4f);
    p = fmaf(s, p, 8.33333333e-3f);
    p = fmaf(s, p, -1.66666667e-1f);
    float res = fmaf(s * r, p, r);
    int ki = (int)k;
    return (ki & 1) ? -res : res;
}

// ---------------- helpers --------------------------------------------------
__device__ __forceinline__ uint32_t smem_u32(const void* p) {
    uint32_t a;
    asm("{ .reg .u64 t; cvta.to.shared.u64 t, %1; cvt.u32.u64 %0, t; }"
        : "=r"(a) : "l"(p));
    return a;
}
__device__ __forceinline__ void ldsm_x4(uint32_t* r, uint32_t addr) {
    asm volatile("ldmatrix.sync.aligned.m8n8.x4.shared.b16 {%0,%1,%2,%3}, [%4];"
                 : "=r"(r[0]), "=r"(r[1]), "=r"(r[2]), "=r"(r[3]) : "r"(addr));
}
__device__ __forceinline__ void mma_f16(float* c, const uint32_t* a,
                                        const uint32_t* b) {
    asm volatile(
        "mma.sync.aligned.m16n8k16.row.col.f32.f16.f16.f32 "
        "{%0,%1,%2,%3}, {%4,%5,%6,%7}, {%8,%9}, {%0,%1,%2,%3};"
        : "+f"(c[0]), "+f"(c[1]), "+f"(c[2]), "+f"(c[3])
        : "r"(a[0]), "r"(a[1]), "r"(a[2]), "r"(a[3]), "r"(b[0]), "r"(b[1]));
}
#define CP_ASYNC16(dst, src) \
    asm volatile("cp.async.cg.shared.global [%0], [%1], 16;" \
                 :: "r"(dst), "l"(src))
#define CP_COMMIT() asm volatile("cp.async.commit_group;")
#define CP_WAIT0()  asm volatile("cp.async.wait_group 0;" ::: "memory")

__device__ __forceinline__ uint32_t packh2(float hi, float lo) {
    uint32_t r;
    asm("cvt.rn.f16x2.f32 %0, %1, %2;" : "=r"(r) : "f"(hi), "f"(lo));
    return r;
}

// ---------------- kernel 0: pack+swizzle qw1 to fp16 -----------------------
__global__ void pack_qw1_kernel(const float* __restrict__ qw1) {
    int idx = blockIdx.x * 256 + threadIdx.x;   // 0..32767 f16x2 words
    int n = idx >> 7;                           // row 0..255
    int kw = idx & 127;                         // k-pair
    int k = kw * 2;
    int cch = k >> 6;                           // chunk
    int kk = k & 63;
    float w0 = qw1[n * HID + k];
    float w1 = qw1[n * HID + k + 1];
    uint32_t hw = packh2(w1, w0);
    uint32_t off = ((n >> 3) << 10) + ((n & 7) << 7) + kk * 2;
    uint32_t sw = off ^ ((off >> 3) & 0x70);
    *(uint32_t*)(g_qpack + cch * 32768 + sw) = hw;
}

// ---------------- kernel 1: branch + premerge ------------------------------
__device__ __forceinline__ void dense_layer(
    const float (*hin)[HID], float (*hout)[HID],
    const float* __restrict__ pw, const float* __restrict__ pb, int t)
{
    float acc[16];
    float bias = pb[t];
#pragma unroll
    for (int r = 0; r < 16; r++) acc[r] = bias;
    const float4* pw4 = (const float4*)pw;
#pragma unroll 4
    for (int k4 = 0; k4 < HID / 4; k4++) {
        float4 w4 = pw4[t * (HID / 4) + k4];
#pragma unroll
        for (int r = 0; r < 16; r++) {
            float4 hv = *(const float4*)&hin[r][k4 * 4];
            acc[r] = fmaf(hv.x, w4.x, acc[r]);
            acc[r] = fmaf(hv.y, w4.y, acc[r]);
            acc[r] = fmaf(hv.z, w4.z, acc[r]);
            acc[r] = fmaf(hv.w, w4.w, acc[r]);
        }
    }
#pragma unroll
    for (int r = 0; r < 16; r++) hout[r][t] = fast_sin(acc[r]);
}

__global__ void branch_kernel(
    const float* __restrict__ x, const float* __restrict__ y,
    const float* __restrict__ bw0, const float* __restrict__ bb0,
    const float* __restrict__ bw1, const float* __restrict__ bb1,
    const float* __restrict__ pw1, const float* __restrict__ pb1,
    const float* __restrict__ pw2, const float* __restrict__ pb2)
{
    int axis = blockIdx.y;
    const float* coord = axis ? y : x;
    const float* bw = axis ? bw1 : bw0;
    const float* bb = axis ? bb1 : bb0;
    float* outf = axis ? g_fy : g_fx;
    int r0 = blockIdx.x * 16;
    int t = threadIdx.x;

    __shared__ __align__(16) float hA[16][HID];
    __shared__ __align__(16) float hB[16][HID];

    float w = bw[t], b = bb[t];
#pragma unroll
    for (int r = 0; r < 16; r++)
        hA[r][t] = fast_sin(fmaf(coord[r0 + r], w, b));
    __syncthreads();
    dense_layer(hA, hB, pw1, pb1, t);
    __syncthreads();
    dense_layer(hB, hA, pw2, pb2, t);
    __syncthreads();
#pragma unroll
    for (int r = 0; r < 16; r++)
        outf[(r0 + r) * HID + t] = hA[r][t];
}

// ---------------- kernel 2: warp-MMA fused GEMM + epilogue -----------------
// grid (8, 1024): i0 = bx*128, j = by. 512 threads = 16 warps (4 M x 4 N).
// Warp tile 32(m) x 64(n). K = 4 chunks of 64, double-buffered, fp16 operands.
// SMEM map:
//   0     fys (1KB) | 1024 qb1s (1KB) | 2048 qw2s (3KB) | 5120 qb2s
//   5632  part[128][4][3] f32 (6KB)
//   12288 stage0: A 16K | B 32K   (48KB)
//   61440 stage1: same
#define SM_FY   0
#define SM_QB1  1024
#define SM_QW2  2048
#define SM_QB2  5120
#define SM_PART 5632
#define SM_STG  12288
#define STG_SZ  49152
#define B_OFF   16384
#define SMEM_TOTAL (SM_STG + 2 * STG_SZ)   // 110592

__global__ __launch_bounds__(512, 1)
void fused_mma_kernel(
    const float* __restrict__ qb1, const float* __restrict__ qw2,
    const float* __restrict__ qb2, float* __restrict__ out)
{
    extern __shared__ __align__(1024) char smem[];
    const uint32_t sb = smem_u32(smem);
    const int tid = threadIdx.x;
    const int wid = tid >> 5;
    const int lane = tid & 31;
    const int wm = wid & 3;          // warp row (M)
    const int wn = wid >> 2;         // warp col (N)
    const int m0w = wm * 32;
    const int n0w = wn * 64;
    const int j = blockIdx.y;
    const int i0 = blockIdx.x * 128;

    float* fys  = (float*)(smem + SM_FY);
    float* qb1s = (float*)(smem + SM_QB1);
    float* qw2s = (float*)(smem + SM_QW2);
    float* qb2s = (float*)(smem + SM_QB2);
    float* part = (float*)(smem + SM_PART);

    // stage small arrays
    if (tid < 256) {
        fys[tid] = g_fy[j * HID + tid];
        qb1s[tid] = qb1[tid];
    }
    for (int e = tid; e < 3 * HID; e += 512) qw2s[e] = qw2[e];
    if (tid < 3) qb2s[tid] = qb2[tid];
    __syncthreads();

    // ---- A build: thread -> row r = tid/4, k-quarter kq = (tid%4)*16 ----
    const int rA = tid >> 2;
    const int kq = (tid & 3) << 4;
    const uint32_t rowoff = ((rA >> 3) << 10) + ((rA & 7) << 7);
    const uint32_t rxor = (rA & 7) << 4;

    auto build_A = [&](int c, uint32_t stg) {
        const float4* fxp = (const float4*)(g_fx + (i0 + rA) * HID + c * 64 + kq);
        const float4* fyp = (const float4*)(fys + c * 64 + kq);
        uint32_t hw[8];
#pragma unroll
        for (int q = 0; q < 4; q++) {
            float4 f = fxp[q];
            float4 g = fyp[q];
            hw[q * 2]     = packh2(f.y * g.y, f.x * g.x);
            hw[q * 2 + 1] = packh2(f.w * g.w, f.z * g.z);
        }
        char* base = smem + stg;
        uint32_t c0 = (uint32_t)(kq * 2);          // byte col 0,32,64,96
        uint32_t o0 = rowoff + (c0 ^ rxor);
        uint32_t o1 = rowoff + ((c0 + 16) ^ rxor);
        *(uint4*)(base + o0) = make_uint4(hw[0], hw[1], hw[2], hw[3]);
        *(uint4*)(base + o1) = make_uint4(hw[4], hw[5], hw[6], hw[7]);
    };
    auto copy_B = [&](int c, uint32_t stg_u32) {
        const char* src = (const char*)g_qpack + c * 32768;
        uint32_t dst = stg_u32 + B_OFF;
#pragma unroll
        for (int e = 0; e < 4; e++) {
            uint32_t off = (uint32_t)(e * 512 + tid) * 16;
            CP_ASYNC16(dst + off, src + off);
        }
        CP_COMMIT();
    };

    // ---- LDSM per-thread row/col components (swizzle applied per k-step) --
    uint32_t rowA[2], xorA[2], colA;
    uint32_t rowB[4], xorB[4], colB;
    colA = (uint32_t)((lane >> 4) << 4);           // 0 or 16 bytes (k0/k8)
#pragma unroll
    for (int mb = 0; mb < 2; mb++) {
        int r = m0w + mb * 16 + (lane & 15);
        rowA[mb] = ((r >> 3) << 10) + ((r & 7) << 7);
        xorA[mb] = (uint32_t)((r & 7) << 4);
    }
    colB = (uint32_t)(((lane >> 3) & 1) << 4);     // 0 or 16 bytes (k0/k8)
#pragma unroll
    for (int nb = 0; nb < 4; nb++) {
        int r = n0w + nb * 16 + (lane & 7) + ((lane >> 4) << 3);
        rowB[nb] = ((r >> 3) << 10) + ((r & 7) << 7);
        xorB[nb] = (uint32_t)((r & 7) << 4);
    }

    float acc[2][8][4];
#pragma unroll
    for (int mb = 0; mb < 2; mb++)
#pragma unroll
        for (int nx = 0; nx < 8; nx++)
#pragma unroll
            for (int e = 0; e < 4; e++) acc[mb][nx][e] = 0.f;

    // ---- prologue: chunk 0 ----
    {
        uint32_t stg = sb + SM_STG;
        copy_B(0, stg);
        build_A(0, SM_STG);
        CP_WAIT0();
        __syncthreads();
    }

    // ---- main loop ----
    for (int c = 0; c < 4; c++) {
        const uint32_t stg = sb + SM_STG + (uint32_t)(c & 1) * STG_SZ;
        if (c < 3) {
            uint32_t nstg = sb + SM_STG + (uint32_t)((c + 1) & 1) * STG_SZ;
            copy_B(c + 1, nstg);
            build_A(c + 1, SM_STG + ((c + 1) & 1) * STG_SZ);
        }
#pragma unroll
        for (int s = 0; s < 4; s++) {
            const uint32_t ks = (uint32_t)(s * 32);
            uint32_t ah[2][4];
#pragma unroll
            for (int mb = 0; mb < 2; mb++) {
                uint32_t adr = stg + rowA[mb] + ((colA + ks) ^ xorA[mb]);
                ldsm_x4(ah[mb], adr);
            }
#pragma unroll
            for (int nb = 0; nb < 4; nb++) {
                uint32_t bh[4];
                uint32_t adr = stg + B_OFF + rowB[nb] + ((colB + ks) ^ xorB[nb]);
                ldsm_x4(bh, adr);
#pragma unroll
                for (int mb = 0; mb < 2; mb++) {
#pragma unroll
                    for (int sub = 0; sub < 2; sub++)
                        mma_f16(acc[mb][nb * 2 + sub], ah[mb], bh + sub * 2);
                }
            }
        }
        if (c < 3) {
            CP_WAIT0();
            __syncthreads();
        }
    }

    // ---- epilogue: sin(acc+qb1) -> 3-ch partial GEMV -> reduce -> out ----
    float p[12];                      // [mb][rh][c]
#pragma unroll
    for (int e = 0; e < 12; e++) p[e] = 0.f;
#pragma unroll
    for (int mb = 0; mb < 2; mb++) {
#pragma unroll
        for (int nx = 0; nx < 8; nx++) {
            int nbase = n0w + nx * 8 + (lane & 3) * 2;
#pragma unroll
            for (int e = 0; e < 4; e++) {
                int n = nbase + (e & 1);
                int rh = e >> 1;
                float hv = fast_sin(acc[mb][nx][e] + qb1s[n]);
                p[(mb * 2 + rh) * 3 + 0] = fmaf(hv, qw2s[n], p[(mb * 2 + rh) * 3 + 0]);
                p[(mb * 2 + rh) * 3 + 1] = fmaf(hv, qw2s[256 + n], p[(mb * 2 + rh) * 3 + 1]);
                p[(mb * 2 + rh) * 3 + 2] = fmaf(hv, qw2s[512 + n], p[(mb * 2 + rh) * 3 + 2]);
            }
        }
    }
#pragma unroll
    for (int d = 1; d <= 2; d <<= 1)
#pragma unroll
        for (int e = 0; e < 12; e++)
            p[e] += __shfl_xor_sync(0xffffffffu, p[e], d);

    if ((lane & 3) == 0) {
#pragma unroll
        for (int mb = 0; mb < 2; mb++)
#pragma unroll
            for (int rh = 0; rh < 2; rh++) {
                int m = m0w + mb * 16 + (lane >> 2) + rh * 8;
#pragma unroll
                for (int cc = 0; cc < 3; cc++)
                    part[(m * 4 + wn) * 3 + cc] = p[(mb * 2 + rh) * 3 + cc];
            }
    }
    __syncthreads();

    if (tid < 384) {
        int m = tid & 127;
        int cc = tid >> 7;
        float s = qb2s[cc];
#pragma unroll
        for (int v = 0; v < 4; v++) s += part[(m * 4 + v) * 3 + cc];
        out[((unsigned)cc * W + j) * H + i0 + m] = 1.f / (1.f + __expf(-s));
    }
}

// ---------------------------------------------------------------------------
extern "C" void kernel_launch(void* const* d_in, const int* in_sizes, int n_in,
                              void* d_out, int out_size)
{
    const float* x   = (const float*)d_in[0];
    const float* y   = (const float*)d_in[1];
    const float* bw0 = (const float*)d_in[2];
    const float* bb0 = (const float*)d_in[3];
    const float* bw1 = (const float*)d_in[4];
    const float* bb1 = (const float*)d_in[5];
    const float* pw1 = (const float*)d_in[6];
    const float* pb1 = (const float*)d_in[7];
    const float* pw2 = (const float*)d_in[8];
    const float* pb2 = (const float*)d_in[9];
    const float* qw1 = (const float*)d_in[10];
    const float* qb1 = (const float*)d_in[11];
    const float* qw2 = (const float*)d_in[12];
    const float* qb2 = (const float*)d_in[13];
    float* out = (float*)d_out;

    cudaFuncSetAttribute(fused_mma_kernel,
                         cudaFuncAttributeMaxDynamicSharedMemorySize, SMEM_TOTAL);

    pack_qw1_kernel<<<128, 256>>>(qw1);
    branch_kernel<<<dim3(H / 16, 2), 256>>>(x, y, bw0, bb0, bw1, bb1,
                                            pw1, pb1, pw2, pb2);
    fused_mma_kernel<<<dim3(8, 1024), 512, SMEM_TOTAL>>>(qb1, qw2, qb2, out);
}

// round 7
// speedup vs baseline: 5.1010x; 1.0908x over previous
#include <cuda_runtime.h>
#include <cuda_bf16.h>
#include <cuda_fp16.h>
#include <cstdint>

#define H 1024
#define W 1024
#define HID 256
#define C 3

typedef unsigned long long u64t;

// ---------------------------------------------------------------------------
// global scratch
// ---------------------------------------------------------------------------
__device__ __align__(16) float g_fx[H * HID];
__device__ __align__(16) float g_fy[W * HID];
// qw1 as fp16, SW128-swizzled K-major tiles. chunk c (k0=64c): 32KB at c*32768
__device__ __align__(16) unsigned char g_qpack[4 * 32768];

// ---------------- fast sine (scalar, branch kernel) ------------------------
__device__ __forceinline__ float fast_sin(float x) {
    const float INV_PI = 0.318309886183790671f;
    float k = rintf(x * INV_PI);
    float r = fmaf(-k, 3.14159274101257324f, x);
    r = fmaf(k, 8.74227765734758577e-8f, r);
    float s = r * r;
    float p = fmaf(s, 2.75573192e-6f, -1.98412698e-4f);
    p = fmaf(s, p, 8.33333333e-3f);
    p = fmaf(s, p, -1.66666667e-1f);
    float res = fmaf(s * r, p, r);
    int ki = (int)k;
    return (ki & 1) ? -res : res;
}

// ---------------- f32x2 packed helpers (sm_100 PTX) ------------------------
__device__ __forceinline__ u64t pk2(float lo, float hi) {
    u64t r;
    asm("mov.b64 %0, {%1, %2};" : "=l"(r)
        : "r"(__float_as_uint(lo)), "r"(__float_as_uint(hi)));
    return r;
}
__device__ __forceinline__ void upk2(u64t v, float& lo, float& hi) {
    uint32_t a, b;
    asm("mov.b64 {%0, %1}, %2;" : "=r"(a), "=r"(b) : "l"(v));
    lo = __uint_as_float(a);
    hi = __uint_as_float(b);
}
__device__ __forceinline__ u64t dup2(float v) { return pk2(v, v); }
__device__ __forceinline__ u64t f2fma(u64t a, u64t b, u64t c) {
    u64t r;
    asm("fma.rn.f32x2 %0, %1, %2, %3;" : "=l"(r) : "l"(a), "l"(b), "l"(c));
    return r;
}
__device__ __forceinline__ u64t f2add(u64t a, u64t b) {
    u64t r;
    asm("add.rn.f32x2 %0, %1, %2;" : "=l"(r) : "l"(a), "l"(b));
    return r;
}
__device__ __forceinline__ u64t f2mul(u64t a, u64t b) {
    u64t r;
    asm("mul.rn.f32x2 %0, %1, %2;" : "=l"(r) : "l"(a), "l"(b));
    return r;
}

// ---------------- misc PTX helpers -----------------------------------------
__device__ __forceinline__ uint32_t smem_u32(const void* p) {
    uint32_t a;
    asm("{ .reg .u64 t; cvta.to.shared.u64 t, %1; cvt.u32.u64 %0, t; }"
        : "=r"(a) : "l"(p));
    return a;
}
__device__ __forceinline__ void ldsm_x4(uint32_t* r, uint32_t addr) {
    asm volatile("ldmatrix.sync.aligned.m8n8.x4.shared.b16 {%0,%1,%2,%3}, [%4];"
                 : "=r"(r[0]), "=r"(r[1]), "=r"(r[2]), "=r"(r[3]) : "r"(addr));
}
__device__ __forceinline__ void mma_f16(float* c, const uint32_t* a,
                                        const uint32_t* b) {
    asm volatile(
        "mma.sync.aligned.m16n8k16.row.col.f32.f16.f16.f32 "
        "{%0,%1,%2,%3}, {%4,%5,%6,%7}, {%8,%9}, {%0,%1,%2,%3};"
        : "+f"(c[0]), "+f"(c[1]), "+f"(c[2]), "+f"(c[3])
        : "r"(a[0]), "r"(a[1]), "r"(a[2]), "r"(a[3]), "r"(b[0]), "r"(b[1]));
}
#define CP_ASYNC16(dst, src) \
    asm volatile("cp.async.cg.shared.global [%0], [%1], 16;" \
                 :: "r"(dst), "l"(src))
#define CP_COMMIT() asm volatile("cp.async.commit_group;")
#define CP_WAIT0()  asm volatile("cp.async.wait_group 0;" ::: "memory")

__device__ __forceinline__ uint32_t packh2(float hi, float lo) {
    uint32_t r;
    asm("cvt.rn.f16x2.f32 %0, %1, %2;" : "=r"(r) : "f"(hi), "f"(lo));
    return r;
}

// ---------------- kernel 0: pack+swizzle qw1 to fp16 -----------------------
__global__ void pack_qw1_kernel(const float* __restrict__ qw1) {
    int idx = blockIdx.x * 256 + threadIdx.x;   // 0..32767 f16x2 words
    int n = idx >> 7;
    int kw = idx & 127;
    int k = kw * 2;
    int cch = k >> 6;
    int kk = k & 63;
    float w0 = qw1[n * HID + k];
    float w1 = qw1[n * HID + k + 1];
    uint32_t hw = packh2(w1, w0);
    uint32_t off = ((n >> 3) << 10) + ((n & 7) << 7) + kk * 2;
    uint32_t sw = off ^ ((off >> 3) & 0x70);
    *(uint32_t*)(g_qpack + cch * 32768 + sw) = hw;
}

// ---------------- kernel 1: branch + premerge ------------------------------
__device__ __forceinline__ void dense_layer(
    const float (*hin)[HID], float (*hout)[HID],
    const float* __restrict__ pw, const float* __restrict__ pb, int t)
{
    float acc[16];
    float bias = pb[t];
#pragma unroll
    for (int r = 0; r < 16; r++) acc[r] = bias;
    const float4* pw4 = (const float4*)pw;
#pragma unroll 4
    for (int k4 = 0; k4 < HID / 4; k4++) {
        float4 w4 = pw4[t * (HID / 4) + k4];
#pragma unroll
        for (int r = 0; r < 16; r++) {
            float4 hv = *(const float4*)&hin[r][k4 * 4];
            acc[r] = fmaf(hv.x, w4.x, acc[r]);
            acc[r] = fmaf(hv.y, w4.y, acc[r]);
            acc[r] = fmaf(hv.z, w4.z, acc[r]);
            acc[r] = fmaf(hv.w, w4.w, acc[r]);
        }
    }
#pragma unroll
    for (int r = 0; r < 16; r++) hout[r][t] = fast_sin(acc[r]);
}

__global__ void branch_kernel(
    const float* __restrict__ x, const float* __restrict__ y,
    const float* __restrict__ bw0, const float* __restrict__ bb0,
    const float* __restrict__ bw1, const float* __restrict__ bb1,
    const float* __restrict__ pw1, const float* __restrict__ pb1,
    const float* __restrict__ pw2, const float* __restrict__ pb2)
{
    int axis = blockIdx.y;
    const float* coord = axis ? y : x;
    const float* bw = axis ? bw1 : bw0;
    const float* bb = axis ? bb1 : bb0;
    float* outf = axis ? g_fy : g_fx;
    int r0 = blockIdx.x * 16;
    int t = threadIdx.x;

    __shared__ __align__(16) float hA[16][HID];
    __shared__ __align__(16) float hB[16][HID];

    float w = bw[t], b = bb[t];
#pragma unroll
    for (int r = 0; r < 16; r++)
        hA[r][t] = fast_sin(fmaf(coord[r0 + r], w, b));
    __syncthreads();
    dense_layer(hA, hB, pw1, pb1, t);
    __syncthreads();
    dense_layer(hB, hA, pw2, pb2, t);
    __syncthreads();
#pragma unroll
    for (int r = 0; r < 16; r++)
        outf[(r0 + r) * HID + t] = hA[r][t];
}

// ---------------- kernel 2: B-resident warp-MMA, j-loop --------------------
// grid (8, 128): i0 = bx*128, j in [by*8, by*8+8). 512 threads = 16 warps.
// B (qw1 fp16, all 4 K-chunks, 128KB) resident in SMEM for the whole CTA.
// Flat pipeline over t = 0..31 (j = t>>2, chunk c = t&3), A double-buffered.
// SMEM map:
//   0      qb1s (1KB) | 1024 qw2s (3KB) | 4096 qb2s | 4608 fys 2x1KB
//   6656   part[128][4][3] f32 (6KB)
//   13312  B 128KB (4 chunks x 32KB, 1024-aligned)
//   144384 A 2 x 16KB
#define SM_QB1  0
#define SM_QW2  1024
#define SM_QB2  4096
#define SM_FY   4608
#define SM_PART 6656
#define SM_B    13312
#define SM_A    144384
#define SMEM_TOTAL 177152

__global__ __launch_bounds__(512, 1)
void fused_mma_kernel(
    const float* __restrict__ qb1, const float* __restrict__ qw2,
    const float* __restrict__ qb2, float* __restrict__ out)
{
    extern __shared__ __align__(1024) char smem[];
    const uint32_t sb = smem_u32(smem);
    const int tid = threadIdx.x;
    const int wid = tid >> 5;
    const int lane = tid & 31;
    const int wm = wid & 3;
    const int wn = wid >> 2;
    const int m0w = wm * 32;
    const int n0w = wn * 64;
    const int i0 = blockIdx.x * 128;
    const int j0 = blockIdx.y * 8;

    float* qb1s = (float*)(smem + SM_QB1);
    float* qw2s = (float*)(smem + SM_QW2);
    float* qb2s = (float*)(smem + SM_QB2);
    float* fys  = (float*)(smem + SM_FY);     // 2 buffers of 256
    float* part = (float*)(smem + SM_PART);

    // ---- one-time staging: B via cp.async, smalls, fy(j0) ----
    {
        const char* src = (const char*)g_qpack;
        uint32_t dst = sb + SM_B;
#pragma unroll
        for (int e = 0; e < 16; e++) {
            uint32_t off = (uint32_t)(e * 512 + tid) * 16;
            CP_ASYNC16(dst + off, src + off);
        }
        CP_COMMIT();
    }
    if (tid < 256) {
        qb1s[tid] = qb1[tid];
        fys[tid] = g_fy[j0 * HID + tid];
    }
    for (int e = tid; e < 3 * HID; e += 512) qw2s[e] = qw2[e];
    if (tid < 3) qb2s[tid] = qb2[tid];
    __syncthreads();

    // ---- A build config: thread -> row rA = tid/4, k-quarter kq ----
    const int rA = tid >> 2;
    const int kq = (tid & 3) << 4;
    const uint32_t rowoff = ((rA >> 3) << 10) + ((rA & 7) << 7);
    const uint32_t rxor = (rA & 7) << 4;

    auto build_A = [&](int c, int abuf, int fyb) {
        const float4* fxp = (const float4*)(g_fx + (i0 + rA) * HID + c * 64 + kq);
        const float4* fyp = (const float4*)(fys + fyb * 256 + c * 64 + kq);
        uint32_t hw[8];
#pragma unroll
        for (int q = 0; q < 4; q++) {
            float4 f = fxp[q];
            float4 g = fyp[q];
            hw[q * 2]     = packh2(f.y * g.y, f.x * g.x);
            hw[q * 2 + 1] = packh2(f.w * g.w, f.z * g.z);
        }
        char* base = smem + SM_A + abuf * 16384;
        uint32_t c0 = (uint32_t)(kq * 2);
        uint32_t o0 = rowoff + (c0 ^ rxor);
        uint32_t o1 = rowoff + ((c0 + 16) ^ rxor);
        *(uint4*)(base + o0) = make_uint4(hw[0], hw[1], hw[2], hw[3]);
        *(uint4*)(base + o1) = make_uint4(hw[4], hw[5], hw[6], hw[7]);
    };

    // ---- LDSM per-thread row/col components ----
    uint32_t rowA[2], xorA[2], colA;
    uint32_t rowB[4], xorB[4], colB;
    colA = (uint32_t)((lane >> 4) << 4);
#pragma unroll
    for (int mb = 0; mb < 2; mb++) {
        int r = m0w + mb * 16 + (lane & 15);
        rowA[mb] = ((r >> 3) << 10) + ((r & 7) << 7);
        xorA[mb] = (uint32_t)((r & 7) << 4);
    }
    colB = (uint32_t)(((lane >> 3) & 1) << 4);
#pragma unroll
    for (int nb = 0; nb < 4; nb++) {
        int r = n0w + nb * 16 + (lane & 7) + ((lane >> 4) << 3);
        rowB[nb] = ((r >> 3) << 10) + ((r & 7) << 7);
        xorB[nb] = (uint32_t)((r & 7) << 4);
    }

    float acc[2][8][4];
#pragma unroll
    for (int mb = 0; mb < 2; mb++)
#pragma unroll
        for (int nx = 0; nx < 8; nx++)
#pragma unroll
            for (int e = 0; e < 4; e++) acc[mb][nx][e] = 0.f;

    // prologue: A(chunk0, j0) into buf0; B must have landed before first MMA
    build_A(0, 0, 0);
    CP_WAIT0();
    __syncthreads();

    // ---- flat pipeline: t = j*4 + c ----
    for (int t = 0; t < 32; t++) {
        const int jj = t >> 2;
        const int c = t & 3;
        const int abuf = t & 1;

        // stage fy for j+1 early in the j (consumed at c==3's build)
        if (c == 0 && jj < 7 && tid < 256)
            fys[((jj + 1) & 1) * 256 + tid] = g_fy[(j0 + jj + 1) * HID + tid];

        // build A for t+1 (chunk (t+1)&3 of j ((t+1)>>2)) into buf (t+1)&1
        if (t < 31)
            build_A((t + 1) & 3, (t + 1) & 1, ((t + 1) >> 2) & 1);

        // MMA over chunk c: A from abuf, B chunk at SM_B + c*32KB
        const uint32_t astg = sb + SM_A + (uint32_t)abuf * 16384;
        const uint32_t bstg = sb + SM_B + (uint32_t)c * 32768;
#pragma unroll
        for (int s = 0; s < 4; s++) {
            const uint32_t ks = (uint32_t)(s * 32);
            uint32_t ah[2][4];
#pragma unroll
            for (int mb = 0; mb < 2; mb++)
                ldsm_x4(ah[mb], astg + rowA[mb] + ((colA + ks) ^ xorA[mb]));
#pragma unroll
            for (int nb = 0; nb < 4; nb++) {
                uint32_t bh[4];
                ldsm_x4(bh, bstg + rowB[nb] + ((colB + ks) ^ xorB[nb]));
#pragma unroll
                for (int mb = 0; mb < 2; mb++) {
#pragma unroll
                    for (int sub = 0; sub < 2; sub++)
                        mma_f16(acc[mb][nb * 2 + sub], ah[mb], bh + sub * 2);
                }
            }
        }

        // ---- epilogue at end of each j (packed f32x2 sin + GEMV) ----
        if (c == 3) {
            const u64t kInv  = dup2(0.15915494309189535f);  // 1/(2pi)
            const u64t kMag  = dup2(12582912.0f);
            const u64t kNMag = dup2(-12582912.0f);
            const u64t kN1   = dup2(-1.0f);
            const u64t c13d = dup2(3.8199526f);
            const u64t c11d = dup2(-15.094643f);
            const u64t c9d  = dup2(42.058694f);
            const u64t c7d  = dup2(-76.705860f);
            const u64t c5d  = dup2(81.605249f);
            const u64t c3d  = dup2(-41.341702f);
            const u64t c1d  = dup2(6.2831853f);

            u64t pr[12];
#pragma unroll
            for (int e = 0; e < 12; e++) pr[e] = pk2(0.f, 0.f);
#pragma unroll
            for (int mb = 0; mb < 2; mb++) {
#pragma unroll
                for (int nx = 0; nx < 8; nx++) {
                    int n = n0w + nx * 8 + (lane & 3) * 2;   // even
                    u64t b2 = *(const u64t*)(qb1s + n);
                    u64t w0 = *(const u64t*)(qw2s + n);
                    u64t w1 = *(const u64t*)(qw2s + 256 + n);
                    u64t w2 = *(const u64t*)(qw2s + 512 + n);
#pragma unroll
                    for (int rh = 0; rh < 2; rh++) {
                        u64t v2 = f2add(pk2(acc[mb][nx][rh * 2],
                                            acc[mb][nx][rh * 2 + 1]), b2);
                        acc[mb][nx][rh * 2] = 0.f;
                        acc[mb][nx][rh * 2 + 1] = 0.f;
                        u64t u2 = f2mul(v2, kInv);
                        u64t y2 = f2add(u2, kMag);
                        u64t k2 = f2add(y2, kNMag);
                        u64t r2 = f2fma(k2, kN1, u2);       // r = u - k
                        u64t s2 = f2mul(r2, r2);
                        u64t p = f2fma(s2, c13d, c11d);
                        p = f2fma(s2, p, c9d);
                        p = f2fma(s2, p, c7d);
                        p = f2fma(s2, p, c5d);
                        p = f2fma(s2, p, c3d);
                        p = f2fma(s2, p, c1d);
                        u64t h2 = f2mul(p, r2);             // sin(2*pi*r)
                        int slot = (mb * 2 + rh) * 3;
                        pr[slot + 0] = f2fma(h2, w0, pr[slot + 0]);
                        pr[slot + 1] = f2fma(h2, w1, pr[slot + 1]);
                        pr[slot + 2] = f2fma(h2, w2, pr[slot + 2]);
                    }
                }
            }
            float p[12];
#pragma unroll
            for (int e = 0; e < 12; e++) {
                float lo, hi;
                upk2(pr[e], lo, hi);
                p[e] = lo + hi;
            }
#pragma unroll
            for (int d = 1; d <= 2; d <<= 1)
#pragma unroll
                for (int e = 0; e < 12; e++)
                    p[e] += __shfl_xor_sync(0xffffffffu, p[e], d);

            if ((lane & 3) == 0) {
#pragma unroll
                for (int mb = 0; mb < 2; mb++)
#pragma unroll
                    for (int rh = 0; rh < 2; rh++) {
                        int m = m0w + mb * 16 + (lane >> 2) + rh * 8;
#pragma unroll
                        for (int cc = 0; cc < 3; cc++)
                            part[(m * 4 + wn) * 3 + cc] = p[(mb * 2 + rh) * 3 + cc];
                    }
            }
            __syncthreads();
            if (tid < 384) {
                int m = tid & 127;
                int cc = tid >> 7;
                float s = qb2s[cc];
#pragma unroll
                for (int v = 0; v < 4; v++) s += part[(m * 4 + v) * 3 + cc];
                out[((unsigned)cc * W + (j0 + jj)) * H + i0 + m] =
                    1.f / (1.f + __expf(-s));
            }
        }
        __syncthreads();
    }
}

// ---------------------------------------------------------------------------
extern "C" void kernel_launch(void* const* d_in, const int* in_sizes, int n_in,
                              void* d_out, int out_size)
{
    const float* x   = (const float*)d_in[0];
    const float* y   = (const float*)d_in[1];
    const float* bw0 = (const float*)d_in[2];
    const float* bb0 = (const float*)d_in[3];
    const float* bw1 = (const float*)d_in[4];
    const float* bb1 = (const float*)d_in[5];
    const float* pw1 = (const float*)d_in[6];
    const float* pb1 = (const float*)d_in[7];
    const float* pw2 = (const float*)d_in[8];
    const float* pb2 = (const float*)d_in[9];
    const float* qw1 = (const float*)d_in[10];
    const float* qb1 = (const float*)d_in[11];
    const float* qw2 = (const float*)d_in[12];
    const float* qb2 = (const float*)d_in[13];
    float* out = (float*)d_out;

    cudaFuncSetAttribute(fused_mma_kernel,
                         cudaFuncAttributeMaxDynamicSharedMemorySize, SMEM_TOTAL);

    pack_qw1_kernel<<<128, 256>>>(qw1);
    branch_kernel<<<dim3(H / 16, 2), 256>>>(x, y, bw0, bb0, bw1, bb1,
                                            pw1, pb1, pw2, pb2);
    fused_mma_kernel<<<dim3(8, 128), 512, SMEM_TOTAL>>>(qb1, qw2, qb2, out);
}

// round 8
// speedup vs baseline: 6.4881x; 1.2719x over previous
#include <cuda_runtime.h>
#include <cuda_bf16.h>
#include <cuda_fp16.h>
#include <cstdint>

#define H 1024
#define W 1024
#define HID 256
#define C 3

typedef unsigned long long u64t;

// ---------------------------------------------------------------------------
// global scratch
// ---------------------------------------------------------------------------
__device__ __align__(16) __half g_fxh[H * HID];
__device__ __align__(16) __half g_fyh[W * HID];
// qw1 as fp16, SW128-swizzled K-major tiles. chunk c (k0=64c): 32KB at c*32768
__device__ __align__(16) unsigned char g_qpack[4 * 32768];

// ---------------- fast sine (scalar, branch kernel) ------------------------
__device__ __forceinline__ float fast_sin(float x) {
    const float INV_PI = 0.318309886183790671f;
    float k = rintf(x * INV_PI);
    float r = fmaf(-k, 3.14159274101257324f, x);
    r = fmaf(k, 8.74227765734758577e-8f, r);
    float s = r * r;
    float p = fmaf(s, 2.75573192e-6f, -1.98412698e-4f);
    p = fmaf(s, p, 8.33333333e-3f);
    p = fmaf(s, p, -1.66666667e-1f);
    float res = fmaf(s * r, p, r);
    int ki = (int)k;
    return (ki & 1) ? -res : res;
}

// ---------------- f32x2 packed helpers -------------------------------------
__device__ __forceinline__ u64t pk2(float lo, float hi) {
    u64t r;
    asm("mov.b64 %0, {%1, %2};" : "=l"(r)
        : "r"(__float_as_uint(lo)), "r"(__float_as_uint(hi)));
    return r;
}
__device__ __forceinline__ void upk2(u64t v, float& lo, float& hi) {
    uint32_t a, b;
    asm("mov.b64 {%0, %1}, %2;" : "=r"(a), "=r"(b) : "l"(v));
    lo = __uint_as_float(a);
    hi = __uint_as_float(b);
}
__device__ __forceinline__ u64t dup2(float v) { return pk2(v, v); }
__device__ __forceinline__ u64t f2fma(u64t a, u64t b, u64t c) {
    u64t r;
    asm("fma.rn.f32x2 %0, %1, %2, %3;" : "=l"(r) : "l"(a), "l"(b), "l"(c));
    return r;
}
__device__ __forceinline__ u64t f2add(u64t a, u64t b) {
    u64t r;
    asm("add.rn.f32x2 %0, %1, %2;" : "=l"(r) : "l"(a), "l"(b));
    return r;
}
__device__ __forceinline__ u64t f2mul(u64t a, u64t b) {
    u64t r;
    asm("mul.rn.f32x2 %0, %1, %2;" : "=l"(r) : "l"(a), "l"(b));
    return r;
}

// ---------------- misc PTX helpers -----------------------------------------
__device__ __forceinline__ uint32_t smem_u32(const void* p) {
    uint32_t a;
    asm("{ .reg .u64 t; cvta.to.shared.u64 t, %1; cvt.u32.u64 %0, t; }"
        : "=r"(a) : "l"(p));
    return a;
}
__device__ __forceinline__ void ldsm_x4(uint32_t* r, uint32_t addr) {
    asm volatile("ldmatrix.sync.aligned.m8n8.x4.shared.b16 {%0,%1,%2,%3}, [%4];"
                 : "=r"(r[0]), "=r"(r[1]), "=r"(r[2]), "=r"(r[3]) : "r"(addr));
}
__device__ __forceinline__ void mma_f16(float* c, const uint32_t* a,
                                        const uint32_t* b) {
    asm volatile(
        "mma.sync.aligned.m16n8k16.row.col.f32.f16.f16.f32 "
        "{%0,%1,%2,%3}, {%4,%5,%6,%7}, {%8,%9}, {%0,%1,%2,%3};"
        : "+f"(c[0]), "+f"(c[1]), "+f"(c[2]), "+f"(c[3])
        : "r"(a[0]), "r"(a[1]), "r"(a[2]), "r"(a[3]), "r"(b[0]), "r"(b[1]));
}
#define CP_ASYNC16(dst, src) \
    asm volatile("cp.async.cg.shared.global [%0], [%1], 16;" \
                 :: "r"(dst), "l"(src))
#define CP_COMMIT() asm volatile("cp.async.commit_group;")
#define CP_WAIT0()  asm volatile("cp.async.wait_group 0;" ::: "memory")

__device__ __forceinline__ uint32_t packh2(float hi, float lo) {
    uint32_t r;
    asm("cvt.rn.f16x2.f32 %0, %1, %2;" : "=r"(r) : "f"(hi), "f"(lo));
    return r;
}
__device__ __forceinline__ uint32_t hmul2(uint32_t a, uint32_t b) {
    uint32_t r;
    asm("mul.rn.f16x2 %0, %1, %2;" : "=r"(r) : "r"(a), "r"(b));
    return r;
}

// ---------------- kernel 0: pack+swizzle qw1 to fp16 -----------------------
__global__ void pack_qw1_kernel(const float* __restrict__ qw1) {
    int idx = blockIdx.x * 256 + threadIdx.x;   // 0..32767 f16x2 words
    int n = idx >> 7;
    int kw = idx & 127;
    int k = kw * 2;
    int cch = k >> 6;
    int kk = k & 63;
    float w0 = qw1[n * HID + k];
    float w1 = qw1[n * HID + k + 1];
    uint32_t hw = packh2(w1, w0);
    uint32_t off = ((n >> 3) << 10) + ((n & 7) << 7) + kk * 2;
    uint32_t sw = off ^ ((off >> 3) & 0x70);
    *(uint32_t*)(g_qpack + cch * 32768 + sw) = hw;
}

// ---------------- kernel 1: branch + premerge (fp16 outputs) ---------------
__device__ __forceinline__ void dense_layer(
    const float (*hin)[HID], float (*hout)[HID],
    const float* __restrict__ pw, const float* __restrict__ pb, int t)
{
    float acc[16];
    float bias = pb[t];
#pragma unroll
    for (int r = 0; r < 16; r++) acc[r] = bias;
    const float4* pw4 = (const float4*)pw;
#pragma unroll 4
    for (int k4 = 0; k4 < HID / 4; k4++) {
        float4 w4 = pw4[t * (HID / 4) + k4];
#pragma unroll
        for (int r = 0; r < 16; r++) {
            float4 hv = *(const float4*)&hin[r][k4 * 4];
            acc[r] = fmaf(hv.x, w4.x, acc[r]);
            acc[r] = fmaf(hv.y, w4.y, acc[r]);
            acc[r] = fmaf(hv.z, w4.z, acc[r]);
            acc[r] = fmaf(hv.w, w4.w, acc[r]);
        }
    }
#pragma unroll
    for (int r = 0; r < 16; r++) hout[r][t] = fast_sin(acc[r]);
}

__global__ void branch_kernel(
    const float* __restrict__ x, const float* __restrict__ y,
    const float* __restrict__ bw0, const float* __restrict__ bb0,
    const float* __restrict__ bw1, const float* __restrict__ bb1,
    const float* __restrict__ pw1, const float* __restrict__ pb1,
    const float* __restrict__ pw2, const float* __restrict__ pb2)
{
    int axis = blockIdx.y;
    const float* coord = axis ? y : x;
    const float* bw = axis ? bw1 : bw0;
    const float* bb = axis ? bb1 : bb0;
    __half* outf = axis ? g_fyh : g_fxh;
    int r0 = blockIdx.x * 16;
    int t = threadIdx.x;

    __shared__ __align__(16) float hA[16][HID];
    __shared__ __align__(16) float hB[16][HID];

    float w = bw[t], b = bb[t];
#pragma unroll
    for (int r = 0; r < 16; r++)
        hA[r][t] = fast_sin(fmaf(coord[r0 + r], w, b));
    __syncthreads();
    dense_layer(hA, hB, pw1, pb1, t);
    __syncthreads();
    dense_layer(hB, hA, pw2, pb2, t);
    __syncthreads();
#pragma unroll
    for (int r = 0; r < 16; r++)
        outf[(r0 + r) * HID + t] = __float2half_rn(hA[r][t]);
}

// ---------------- kernel 2: B-resident warp-MMA, j-loop, fp16 A-build ------
// grid (8, 128): i0 = bx*128, j in [by*8, by*8+8). 512 threads = 16 warps.
// SMEM map:
//   0      qb1s/2pi (1KB) | 1024 qw2s (3KB) | 4096 qb2s | 4608 fyh 2x512B
//   5632   part[128][4][3] f32 (6KB)
//   13312  B 128KB (4 chunks x 32KB, 1024-aligned)
//   144384 A 2 x 16KB
#define SM_QB1  0
#define SM_QW2  1024
#define SM_QB2  4096
#define SM_FYH  4608
#define SM_PART 5632
#define SM_B    13312
#define SM_A    144384
#define SMEM_TOTAL 177152

__global__ __launch_bounds__(512, 1)
void fused_mma_kernel(
    const float* __restrict__ qb1, const float* __restrict__ qw2,
    const float* __restrict__ qb2, float* __restrict__ out)
{
    extern __shared__ __align__(1024) char smem[];
    const uint32_t sb = smem_u32(smem);
    const int tid = threadIdx.x;
    const int wid = tid >> 5;
    const int lane = tid & 31;
    const int wm = wid & 3;
    const int wn = wid >> 2;
    const int m0w = wm * 32;
    const int n0w = wn * 64;
    const int i0 = blockIdx.x * 128;
    const int j0 = blockIdx.y * 8;

    float* qb1s = (float*)(smem + SM_QB1);     // pre-scaled by 1/(2pi)
    float* qw2s = (float*)(smem + SM_QW2);
    float* qb2s = (float*)(smem + SM_QB2);
    uint32_t* fyhs = (uint32_t*)(smem + SM_FYH);   // 2 buffers x 128 h2 words
    float* part = (float*)(smem + SM_PART);

    // ---- one-time staging: B via cp.async, smalls, fyh(j0) ----
    {
        const char* src = (const char*)g_qpack;
        uint32_t dst = sb + SM_B;
#pragma unroll
        for (int e = 0; e < 16; e++) {
            uint32_t off = (uint32_t)(e * 512 + tid) * 16;
            CP_ASYNC16(dst + off, src + off);
        }
        CP_COMMIT();
    }
    if (tid < 256) qb1s[tid] = qb1[tid] * 0.15915494309189535f;
    if (tid >= 256 && tid < 384)
        fyhs[tid - 256] = ((const uint32_t*)(g_fyh + (size_t)j0 * HID))[tid - 256];
    for (int e = tid; e < 3 * HID; e += 512) qw2s[e] = qw2[e];
    if (tid < 3) qb2s[tid] = qb2[tid];
    __syncthreads();

    // ---- A build config: thread -> row rA = tid/4, k-quarter kq ----
    const int rA = tid >> 2;
    const int kq = (tid & 3) << 4;             // k offset within 64-chunk
    const uint32_t rowoff = ((rA >> 3) << 10) + ((rA & 7) << 7);
    const uint32_t rxor = (rA & 7) << 4;

    uint4 pf0, pf1;                            // prefetched fx fp16 (16 halves)
    auto load_pf = [&](int c) {
        const uint4* p = (const uint4*)(g_fxh + (size_t)(i0 + rA) * HID + c * 64 + kq);
        pf0 = p[0];
        pf1 = p[1];
    };
    auto build_A_pf = [&](int abuf, int fyb, int c) {
        const uint4* fyp = (const uint4*)((char*)fyhs + fyb * 512 + (c * 64 + kq) * 2);
        uint4 g0 = fyp[0], g1 = fyp[1];
        uint32_t hw[8];
        hw[0] = hmul2(pf0.x, g0.x); hw[1] = hmul2(pf0.y, g0.y);
        hw[2] = hmul2(pf0.z, g0.z); hw[3] = hmul2(pf0.w, g0.w);
        hw[4] = hmul2(pf1.x, g1.x); hw[5] = hmul2(pf1.y, g1.y);
        hw[6] = hmul2(pf1.z, g1.z); hw[7] = hmul2(pf1.w, g1.w);
        char* base = smem + SM_A + abuf * 16384;
        uint32_t c0 = (uint32_t)(kq * 2);
        uint32_t o0 = rowoff + (c0 ^ rxor);
        uint32_t o1 = rowoff + ((c0 + 16) ^ rxor);
        *(uint4*)(base + o0) = make_uint4(hw[0], hw[1], hw[2], hw[3]);
        *(uint4*)(base + o1) = make_uint4(hw[4], hw[5], hw[6], hw[7]);
    };

    // ---- LDSM per-thread row/col components ----
    uint32_t rowA[2], xorA[2], colA;
    uint32_t rowB[4], xorB[4], colB;
    colA = (uint32_t)((lane >> 4) << 4);
#pragma unroll
    for (int mb = 0; mb < 2; mb++) {
        int r = m0w + mb * 16 + (lane & 15);
        rowA[mb] = ((r >> 3) << 10) + ((r & 7) << 7);
        xorA[mb] = (uint32_t)((r & 7) << 4);
    }
    colB = (uint32_t)(((lane >> 3) & 1) << 4);
#pragma unroll
    for (int nb = 0; nb < 4; nb++) {
        int r = n0w + nb * 16 + (lane & 7) + ((lane >> 4) << 3);
        rowB[nb] = ((r >> 3) << 10) + ((r & 7) << 7);
        xorB[nb] = (uint32_t)((r & 7) << 4);
    }

    float acc[2][8][4];
#pragma unroll
    for (int mb = 0; mb < 2; mb++)
#pragma unroll
        for (int nx = 0; nx < 8; nx++)
#pragma unroll
            for (int e = 0; e < 4; e++) acc[mb][nx][e] = 0.f;

    // prologue: build A(t=0) directly, prefetch chunk for t=1's build
    load_pf(0);
    build_A_pf(0, 0, 0);
    load_pf(1);
    CP_WAIT0();
    __syncthreads();

    // ---- flat pipeline: t = j*4 + c ----
    for (int t = 0; t < 32; t++) {
        const int jj = t >> 2;
        const int c = t & 3;
        const int abuf = t & 1;

        // stage fyh for j+1 early in the j (consumed at c==3's build)
        if (c == 0 && jj < 7 && tid < 128)
            fyhs[((jj + 1) & 1) * 128 + tid] =
                ((const uint32_t*)(g_fyh + (size_t)(j0 + jj + 1) * HID))[tid];

        // build A for t+1 from prefetched regs; then prefetch for t+2
        if (t < 31)
            build_A_pf((t + 1) & 1, ((t + 1) >> 2) & 1, (t + 1) & 3);
        if (t < 30)
            load_pf((t + 2) & 3);

        // MMA over chunk c: A from abuf, B chunk at SM_B + c*32KB
        const uint32_t astg = sb + SM_A + (uint32_t)abuf * 16384;
        const uint32_t bstg = sb + SM_B + (uint32_t)c * 32768;
#pragma unroll
        for (int s = 0; s < 4; s++) {
            const uint32_t ks = (uint32_t)(s * 32);
            uint32_t ah[2][4];
#pragma unroll
            for (int mb = 0; mb < 2; mb++)
                ldsm_x4(ah[mb], astg + rowA[mb] + ((colA + ks) ^ xorA[mb]));
#pragma unroll
            for (int nb = 0; nb < 4; nb++) {
                uint32_t bh[4];
                ldsm_x4(bh, bstg + rowB[nb] + ((colB + ks) ^ xorB[nb]));
#pragma unroll
                for (int mb = 0; mb < 2; mb++) {
#pragma unroll
                    for (int sub = 0; sub < 2; sub++)
                        mma_f16(acc[mb][nb * 2 + sub], ah[mb], bh + sub * 2);
                }
            }
        }

        // ---- epilogue at end of each j (packed f32x2 sin + GEMV) ----
        if (c == 3) {
            const u64t kInv  = dup2(0.15915494309189535f);  // 1/(2pi)
            const u64t kMag  = dup2(12582912.0f);
            const u64t kNMag = dup2(-12582912.0f);
            const u64t kN1   = dup2(-1.0f);
            const u64t c13d = dup2(3.8199526f);
            const u64t c11d = dup2(-15.094643f);
            const u64t c9d  = dup2(42.058694f);
            const u64t c7d  = dup2(-76.705860f);
            const u64t c5d  = dup2(81.605249f);
            const u64t c3d  = dup2(-41.341702f);
            const u64t c1d  = dup2(6.2831853f);

            u64t pr[12];
#pragma unroll
            for (int e = 0; e < 12; e++) pr[e] = pk2(0.f, 0.f);
#pragma unroll
            for (int mb = 0; mb < 2; mb++) {
#pragma unroll
                for (int nx = 0; nx < 8; nx++) {
                    int n = n0w + nx * 8 + (lane & 3) * 2;   // even
                    u64t b2 = *(const u64t*)(qb1s + n);      // qb1/(2pi)
                    u64t w0 = *(const u64t*)(qw2s + n);
                    u64t w1 = *(const u64t*)(qw2s + 256 + n);
                    u64t w2 = *(const u64t*)(qw2s + 512 + n);
#pragma unroll
                    for (int rh = 0; rh < 2; rh++) {
                        u64t a2 = pk2(acc[mb][nx][rh * 2],
                                      acc[mb][nx][rh * 2 + 1]);
                        acc[mb][nx][rh * 2] = 0.f;
                        acc[mb][nx][rh * 2 + 1] = 0.f;
                        u64t u2 = f2fma(a2, kInv, b2);      // (h+qb1)/(2pi)
                        u64t y2 = f2add(u2, kMag);
                        u64t k2 = f2add(y2, kNMag);
                        u64t r2 = f2fma(k2, kN1, u2);       // r = u - round(u)
                        u64t s2 = f2mul(r2, r2);
                        u64t p = f2fma(s2, c13d, c11d);
                        p = f2fma(s2, p, c9d);
                        p = f2fma(s2, p, c7d);
                        p = f2fma(s2, p, c5d);
                        p = f2fma(s2, p, c3d);
                        p = f2fma(s2, p, c1d);
                        u64t h2 = f2mul(p, r2);             // sin(2*pi*r)
                        int slot = (mb * 2 + rh) * 3;
                        pr[slot + 0] = f2fma(h2, w0, pr[slot + 0]);
                        pr[slot + 1] = f2fma(h2, w1, pr[slot + 1]);
                        pr[slot + 2] = f2fma(h2, w2, pr[slot + 2]);
                    }
                }
            }
            float p[12];
#pragma unroll
            for (int e = 0; e < 12; e++) {
                float lo, hi;
                upk2(pr[e], lo, hi);
                p[e] = lo + hi;
            }
#pragma unroll
            for (int d = 1; d <= 2; d <<= 1)
#pragma unroll
                for (int e = 0; e < 12; e++)
                    p[e] += __shfl_xor_sync(0xffffffffu, p[e], d);

            if ((lane & 3) == 0) {
#pragma unroll
                for (int mb = 0; mb < 2; mb++)
#pragma unroll
                    for (int rh = 0; rh < 2; rh++) {
                        int m = m0w + mb * 16 + (lane >> 2) + rh * 8;
#pragma unroll
                        for (int cc = 0; cc < 3; cc++)
                            part[(m * 4 + wn) * 3 + cc] = p[(mb * 2 + rh) * 3 + cc];
                    }
            }
            __syncthreads();
            if (tid < 384) {
                int m = tid & 127;
                int cc = tid >> 7;
                float s = qb2s[cc];
#pragma unroll
                for (int v = 0; v < 4; v++) s += part[(m * 4 + v) * 3 + cc];
                out[((unsigned)cc * W + (j0 + jj)) * H + i0 + m] =
                    1.f / (1.f + __expf(-s));
            }
        }
        __syncthreads();
    }
}

// ---------------------------------------------------------------------------
extern "C" void kernel_launch(void* const* d_in, const int* in_sizes, int n_in,
                              void* d_out, int out_size)
{
    const float* x   = (const float*)d_in[0];
    const float* y   = (const float*)d_in[1];
    const float* bw0 = (const float*)d_in[2];
    const float* bb0 = (const float*)d_in[3];
    const float* bw1 = (const float*)d_in[4];
    const float* bb1 = (const float*)d_in[5];
    const float* pw1 = (const float*)d_in[6];
    const float* pb1 = (const float*)d_in[7];
    const float* pw2 = (const float*)d_in[8];
    const float* pb2 = (const float*)d_in[9];
    const float* qw1 = (const float*)d_in[10];
    const float* qb1 = (const float*)d_in[11];
    const float* qw2 = (const float*)d_in[12];
    const float* qb2 = (const float*)d_in[13];
    float* out = (float*)d_out;

    cudaFuncSetAttribute(fused_mma_kernel,
                         cudaFuncAttributeMaxDynamicSharedMemorySize, SMEM_TOTAL);

    pack_qw1_kernel<<<128, 256>>>(qw1);
    branch_kernel<<<dim3(H / 16, 2), 256>>>(x, y, bw0, bb0, bw1, bb1,
                                            pw1, pb1, pw2, pb2);
    fused_mma_kernel<<<dim3(8, 128), 512, SMEM_TOTAL>>>(qb1, qw2, qb2, out);
}